// round 7
// baseline (speedup 1.0000x reference)
#include <cuda_runtime.h>
#include <cuda_bf16.h>

#define IMAGE_SIZE 32
#define T_MAX 50
#define D2_LUT 206   // masks are exactly 1.0f for d2 >= 205 (exp < 2^-25 rounds away)

// ---------- compile-time LUT ----------
constexpr double cexp(double x) {
    const double LN2 = 0.6931471805599453;
    const double INV_LN2 = 1.4426950408889634;
    double tt = x * INV_LN2;
    int n = (int)(tt >= 0.0 ? tt + 0.5 : tt - 0.5);
    double r = x - (double)n * LN2;          // |r| <= 0.3466
    double s = 1.0, term = 1.0;
    for (int k = 1; k <= 13; k++) { term *= r / (double)k; s += term; }
    double p = 1.0;
    int m = n;
    while (m <= -16) { p *= 0.0000152587890625; m += 16; }  // 2^-16
    while (m < 0)    { p *= 0.5;  m++; }
    while (m > 0)    { p *= 2.0;  m--; }
    return s * p;
}

struct Lut {
    float v[T_MAX * D2_LUT];
    constexpr Lut() : v{} {
        for (int d2 = 0; d2 < D2_LUT; d2++) {
            double m = 1.0;
            for (int i = 1; i <= T_MAX; i++) {
                double beta = 1.0 + 0.1 * (double)(i - 1);
                double g = cexp(-(double)d2 / (2.0 * beta));
                m *= (1.0 - g);
                v[(i - 1) * D2_LUT + d2] = (d2 >= 205) ? 1.0f : (float)m;
            }
        }
    }
};

__device__ constexpr Lut g_lut{};

// ---------- single streaming kernel ----------
// One block = 2 consecutive images, 256 threads, each thread serves BOTH
// images at the same (y, xbase): 6 independent float4 loads issued up front
// (96B in flight per thread), 8 LUT gathers, 6 stores.
__global__ __launch_bounds__(256)
void apply_mask_kernel(const float* __restrict__ x0,
                       const int*   __restrict__ t,
                       const float* __restrict__ cx,
                       const float* __restrict__ cy,
                       float* __restrict__ out) {
    int tid = threadIdx.x;
    int bA  = blockIdx.x * 2;
    int bB  = bA + 1;
    int y     = tid >> 3;      // 0..31
    int xbase = (tid & 7) << 2; // 0,4,...,28

    size_t pixA = (size_t)bA * 3072 + (size_t)y * IMAGE_SIZE + xbase;
    size_t pixB = pixA + 3072;

    // 6 independent streaming loads in flight.
    float4 a0 = __ldg(reinterpret_cast<const float4*>(x0 + pixA));
    float4 a1 = __ldg(reinterpret_cast<const float4*>(x0 + pixA + 1024));
    float4 a2 = __ldg(reinterpret_cast<const float4*>(x0 + pixA + 2048));
    float4 b0 = __ldg(reinterpret_cast<const float4*>(x0 + pixB));
    float4 b1 = __ldg(reinterpret_cast<const float4*>(x0 + pixB + 1024));
    float4 b2 = __ldg(reinterpret_cast<const float4*>(x0 + pixB + 2048));

    // Per-image params (uniform across block -> broadcast).
    float cxA = __ldg(&cx[bA]), cyA = __ldg(&cy[bA]);
    float cxB = __ldg(&cx[bB]), cyB = __ldg(&cy[bB]);
    int   tA  = __ldg(&t[bA]),  tB  = __ldg(&t[bB]);

    float fy = (float)y;
    float fx0 = (float)(xbase + 0), fx1 = (float)(xbase + 1);
    float fx2 = (float)(xbase + 2), fx3 = (float)(xbase + 3);

    // Image A masks
    {
        float dy = fy - cyA; float dy2 = dy * dy;
        float e0 = fx0 - cxA, e1 = fx1 - cxA, e2 = fx2 - cxA, e3 = fx3 - cxA;
        const float* __restrict__ lrow = g_lut.v + (tA - 1) * D2_LUT;
        float m0 = __ldg(&lrow[min((int)(e0 * e0 + dy2), 205)]);
        float m1 = __ldg(&lrow[min((int)(e1 * e1 + dy2), 205)]);
        float m2 = __ldg(&lrow[min((int)(e2 * e2 + dy2), 205)]);
        float m3 = __ldg(&lrow[min((int)(e3 * e3 + dy2), 205)]);
        a0.x *= m0; a0.y *= m1; a0.z *= m2; a0.w *= m3;
        a1.x *= m0; a1.y *= m1; a1.z *= m2; a1.w *= m3;
        a2.x *= m0; a2.y *= m1; a2.z *= m2; a2.w *= m3;
    }
    *reinterpret_cast<float4*>(out + pixA)        = a0;
    *reinterpret_cast<float4*>(out + pixA + 1024) = a1;
    *reinterpret_cast<float4*>(out + pixA + 2048) = a2;

    // Image B masks
    {
        float dy = fy - cyB; float dy2 = dy * dy;
        float e0 = fx0 - cxB, e1 = fx1 - cxB, e2 = fx2 - cxB, e3 = fx3 - cxB;
        const float* __restrict__ lrow = g_lut.v + (tB - 1) * D2_LUT;
        float m0 = __ldg(&lrow[min((int)(e0 * e0 + dy2), 205)]);
        float m1 = __ldg(&lrow[min((int)(e1 * e1 + dy2), 205)]);
        float m2 = __ldg(&lrow[min((int)(e2 * e2 + dy2), 205)]);
        float m3 = __ldg(&lrow[min((int)(e3 * e3 + dy2), 205)]);
        b0.x *= m0; b0.y *= m1; b0.z *= m2; b0.w *= m3;
        b1.x *= m0; b1.y *= m1; b1.z *= m2; b1.w *= m3;
        b2.x *= m0; b2.y *= m1; b2.z *= m2; b2.w *= m3;
    }
    *reinterpret_cast<float4*>(out + pixB)        = b0;
    *reinterpret_cast<float4*>(out + pixB + 1024) = b1;
    *reinterpret_cast<float4*>(out + pixB + 2048) = b2;
}

extern "C" void kernel_launch(void* const* d_in, const int* in_sizes, int n_in,
                              void* d_out, int out_size) {
    const float* x0 = (const float*)d_in[0];
    const int*   t  = (const int*)d_in[1];
    const float* cx = (const float*)d_in[2];
    const float* cy = (const float*)d_in[3];
    float* out = (float*)d_out;

    int B = in_sizes[1];  // t has B elements

    apply_mask_kernel<<<B / 2, 256>>>(x0, t, cx, cy, out);
}